// round 1
// baseline (speedup 1.0000x reference)
#include <cuda_runtime.h>
#include <cuda_bf16.h>

// Problem constants
#define NROWS 8192
#define NCOLS 8192   // K dimension of adj @ features
#define F     64
#define OUTF  64

// ---------------- scratch (no cudaMalloc allowed) ----------------
__device__ float g_neigh[NROWS * F];   // adj@x / (deg+1), 2 MB

// ================= Kernel 1: neigh = (adj @ x) / (rowsum(adj)+1) =================
// BM=64 rows per block, BN=64 (=F), BK=16. 256 threads, 4x4 microtile.
#define BM 64
#define BN 64
#define BK 16

__global__ __launch_bounds__(256, 1)
void sage_neigh_kernel(const float* __restrict__ adj,
                       const float* __restrict__ feat,
                       float* __restrict__ neigh_out)
{
    __shared__ float As[BM * BK];   // [row][k]
    __shared__ float Bs[BK * BN];   // [k][col]
    __shared__ float degsm[BM];

    const int tid = threadIdx.x;
    const int tx  = tid & 15;        // 0..15 -> col group (4 cols)
    const int ty  = tid >> 4;        // 0..15 -> row group (4 rows)
    const int row0 = blockIdx.x * BM;

    // Global load mapping: one float4 per thread per tile
    const int a_row  = tid >> 2;          // 0..63
    const int a_col  = (tid & 3) * 4;     // 0,4,8,12
    const int b_krow = tid >> 4;          // 0..15
    const int b_col  = (tid & 15) * 4;    // 0..60

    const float* a_gptr = adj  + (size_t)(row0 + a_row) * NCOLS + a_col;
    const float* b_gptr = feat + (size_t)b_krow * F + b_col;

    float acc[4][4] = {};
    float dacc[4]   = {};   // row-degree partials (only tx==0 uses)

    for (int k0 = 0; k0 < NCOLS; k0 += BK) {
        float4 av = *(const float4*)(a_gptr + k0);
        float4 bv = *(const float4*)(b_gptr + (size_t)k0 * F);
        *(float4*)(As + a_row * BK + a_col) = av;
        *(float4*)(Bs + b_krow * BN + b_col) = bv;
        __syncthreads();

        #pragma unroll
        for (int k = 0; k < BK; k++) {
            float a[4];
            #pragma unroll
            for (int i = 0; i < 4; i++)
                a[i] = As[(ty * 4 + i) * BK + k];
            float4 b = *(const float4*)(Bs + k * BN + tx * 4);
            #pragma unroll
            for (int i = 0; i < 4; i++) {
                acc[i][0] = fmaf(a[i], b.x, acc[i][0]);
                acc[i][1] = fmaf(a[i], b.y, acc[i][1]);
                acc[i][2] = fmaf(a[i], b.z, acc[i][2]);
                acc[i][3] = fmaf(a[i], b.w, acc[i][3]);
            }
            if (tx == 0) {
                #pragma unroll
                for (int i = 0; i < 4; i++) dacc[i] += a[i];
            }
        }
        __syncthreads();
    }

    if (tx == 0) {
        #pragma unroll
        for (int i = 0; i < 4; i++)
            degsm[ty * 4 + i] = dacc[i] + 1.0f;
    }
    __syncthreads();

    #pragma unroll
    for (int i = 0; i < 4; i++) {
        const int r = row0 + ty * 4 + i;
        const float inv = 1.0f / degsm[ty * 4 + i];
        float4 v;
        v.x = acc[i][0] * inv;
        v.y = acc[i][1] * inv;
        v.z = acc[i][2] * inv;
        v.w = acc[i][3] * inv;
        *(float4*)(neigh_out + (size_t)r * F + tx * 4) = v;
    }
}

// ================= Kernel 2: out = [x || neigh] @ W^T =================
// 32 rows per block, K=128, 64 output cols. 256 threads.
// SMEM: Wsm[k][o] (transposed, conflict-free) 32KB + dsm[32][128] 16KB = 48KB.
__global__ __launch_bounds__(256, 1)
void sage_proj_kernel(const float* __restrict__ feat,
                      const float* __restrict__ neigh,
                      const float* __restrict__ W,
                      float* __restrict__ out)
{
    __shared__ float Wsm[128 * 64];   // Wsm[k*64+o] = W[o*128+k]
    __shared__ float dsm[32 * 128];   // [row][k]: k<64 = feat, k>=64 = neigh

    const int tid  = threadIdx.x;
    const int row0 = blockIdx.x * 32;

    // Load W transposed (8192 elements / 256 threads = 32 each)
    for (int idx = tid; idx < OUTF * 128; idx += 256) {
        int o = idx >> 7;        // /128
        int k = idx & 127;
        Wsm[k * 64 + o] = W[idx];
    }
    // Load data rows: 32 rows x 16 float4 (feat) + same (neigh)
    for (int idx = tid; idx < 32 * 16; idx += 256) {
        int r  = idx >> 4;
        int c4 = (idx & 15) * 4;
        *(float4*)(dsm + r * 128 + c4) =
            *(const float4*)(feat + (size_t)(row0 + r) * F + c4);
        *(float4*)(dsm + r * 128 + 64 + c4) =
            *(const float4*)(neigh + (size_t)(row0 + r) * F + c4);
    }
    __syncthreads();

    const int c  = tid & 63;    // output col
    const int rs = tid >> 6;    // 0..3

    #pragma unroll
    for (int rr = 0; rr < 8; rr++) {
        const int r = rs + rr * 4;
        float acc = 0.f;
        #pragma unroll
        for (int k = 0; k < 128; k++)
            acc = fmaf(dsm[r * 128 + k], Wsm[k * 64 + c], acc);
        out[(size_t)(row0 + r) * OUTF + c] = acc;
    }
}

// ================= launch =================
extern "C" void kernel_launch(void* const* d_in, const int* in_sizes, int n_in,
                              void* d_out, int out_size)
{
    const float* adj  = (const float*)d_in[0];   // [8192, 8192]
    const float* feat = (const float*)d_in[1];   // [8192, 64]
    const float* W    = (const float*)d_in[2];   // [64, 128]
    float* out = (float*)d_out;                  // [8192, 64]

    float* neigh;
    cudaGetSymbolAddress((void**)&neigh, g_neigh);

    sage_neigh_kernel<<<NROWS / BM, 256>>>(adj, feat, neigh);
    sage_proj_kernel<<<NROWS / 32, 256>>>(feat, neigh, W, out);
}

// round 7
// speedup vs baseline: 4.9681x; 4.9681x over previous
#include <cuda_runtime.h>
#include <cuda_bf16.h>
#include <cstdint>

// ---------------- problem constants ----------------
#define NROWS 8192
#define NCOLS 8192
#define F     64
#define OUTF  64

// ---------------- scratch (no cudaMalloc allowed) ----------------
__device__ float         g_part[2 * NROWS * F];       // split-K partial adj@x (4 MB)
__device__ float         g_deg[2 * NROWS];            // split-K partial rowsum
__device__ __nv_bfloat16 g_featT[(size_t)F * NCOLS];  // feat transposed, bf16, K-major (1 MB)

// ================= helpers =================
__device__ __forceinline__ uint32_t smem_u32(const void* p) {
    uint32_t a;
    asm("{ .reg .u64 t; cvta.to.shared.u64 t, %1; cvt.u32.u64 %0, t; }" : "=r"(a) : "l"(p));
    return a;
}
#define CP_ASYNC16(dst, src) \
    asm volatile("cp.async.cg.shared.global [%0], [%1], 16;" :: "r"(dst), "l"(src) : "memory")
#define CP_ASYNC_COMMIT() asm volatile("cp.async.commit_group;" ::: "memory")
#define CP_ASYNC_WAIT1()  asm volatile("cp.async.wait_group 1;" ::: "memory")

__device__ __forceinline__ void ldsm4(uint32_t* r, uint32_t addr) {
    asm volatile("ldmatrix.sync.aligned.m8n8.x4.shared.b16 {%0,%1,%2,%3}, [%4];"
                 : "=r"(r[0]), "=r"(r[1]), "=r"(r[2]), "=r"(r[3]) : "r"(addr));
}
__device__ __forceinline__ void mma16816(float* d, const uint32_t* a, const uint32_t* b) {
    asm volatile("mma.sync.aligned.m16n8k16.row.col.f32.bf16.bf16.f32 "
                 "{%0,%1,%2,%3},{%4,%5,%6,%7},{%8,%9},{%0,%1,%2,%3};"
                 : "+f"(d[0]), "+f"(d[1]), "+f"(d[2]), "+f"(d[3])
                 : "r"(a[0]), "r"(a[1]), "r"(a[2]), "r"(a[3]), "r"(b[0]), "r"(b[1]));
}

// ================= Kernel 0: featT[n][k] = bf16(feat[k][n]) =================
__global__ __launch_bounds__(256, 1)
void sage_featT_kernel(const float* __restrict__ feat, __nv_bfloat16* __restrict__ featT)
{
    __shared__ __nv_bfloat16 ts[64 * 129];
    const int k0 = blockIdx.x * 128;
    const int tid = threadIdx.x;
    for (int j = tid; j < 128 * 64; j += 256) {
        int k = j >> 6, n = j & 63;
        ts[n * 129 + k] = __float2bfloat16(feat[(size_t)(k0 + k) * F + n]);
    }
    __syncthreads();
    for (int j = tid; j < 64 * 64; j += 256) {
        int n = j >> 6, kk = (j & 63) * 2;
        __nv_bfloat162 v;
        v.x = ts[n * 129 + kk];
        v.y = ts[n * 129 + kk + 1];
        *(__nv_bfloat162*)(featT + (size_t)n * NCOLS + k0 + kk) = v;
    }
}

// ================= Kernel 1: split-K partial adj@featT^T + rowsum (HMMA bf16) =================
// CTA: M=128 rows, N=64, K-chunk 64. Grid (64, 2). 8 warps, each 32x32 output tile.
#define BKC 64
#define KSPLIT 2
#define KPER (NCOLS / KSPLIT)       // 4096
#define NCHUNK (KPER / BKC)         // 64

// smem byte offsets: A double (128x64 bf16 = 16KB each), B triple (64x64 bf16 = 8KB each)
#define SM_A0 0
#define SM_A1 16384
#define SM_B0 32768
#define SM_B1 40960
#define SM_B2 49152
#define SM1_TOTAL 57344

__global__ __launch_bounds__(256, 1)
void sage_neigh_mma(const float* __restrict__ adj,
                    const __nv_bfloat16* __restrict__ featT,
                    float* __restrict__ part,
                    float* __restrict__ degp)
{
    extern __shared__ char smem[];
    const uint32_t smem_base = smem_u32(smem);
    const int tid  = threadIdx.x;
    const int wid  = tid >> 5;
    const int lid  = tid & 31;
    const int row0 = blockIdx.x * 128;
    const int kz   = blockIdx.y;
    const size_t kbase = (size_t)kz * KPER;

    // ---- A global-load mapping: rows rbase+16s (s=0..7), float4 col col4 ----
    const int col4  = tid & 15;
    const int rbase = tid >> 4;
    const float* ap = adj + (size_t)(row0 + rbase) * NCOLS + kbase + col4 * 4;

    const uint32_t a_off[2] = {SM_A0, SM_A1};
    const uint32_t b_off[3] = {SM_B0, SM_B1, SM_B2};

    // ---- warp MMA tile: rows [wr0, wr0+32), cols [wc0, wc0+32) ----
    const int wr0 = (wid >> 1) * 32;
    const int wc0 = (wid & 1) * 32;
    const int lg  = lid >> 3;       // ldmatrix address group 0..3
    const int lr  = lid & 7;

    // A ldmatrix addressing: mf selects 16-row half. group: (lg&1)*8 row, (lg>>1)*16 kbyte
    int arow[2], asx[2];
    uint32_t abaseoff[2];
    #pragma unroll
    for (int mf = 0; mf < 2; mf++) {
        arow[mf] = wr0 + mf * 16 + (lg & 1) * 8 + lr;
        asx[mf]  = (arow[mf] & 7) << 4;
        abaseoff[mf] = (uint32_t)arow[mf] * 128;
    }
    const int akb = (lg >> 1) * 16;
    // B ldmatrix addressing: bg selects 16-n half. group: (lg>>1)*8 n, (lg&1)*16 kbyte
    int bn[2], bsx[2];
    uint32_t bbaseoff[2];
    #pragma unroll
    for (int bg = 0; bg < 2; bg++) {
        bn[bg] = wc0 + bg * 16 + (lg >> 1) * 8 + lr;
        bsx[bg] = (bn[bg] & 7) << 4;
        bbaseoff[bg] = (uint32_t)bn[bg] * 128;
    }
    const int bkb = (lg & 1) * 16;

    // ---- prolog: B chunk 0 via cp.async; A chunk 0 into regs ----
    {
        const __nv_bfloat16* src0 = featT + kbase;
        #pragma unroll
        for (int s2 = 0; s2 < 2; s2++) {
            int j = tid + 256 * s2;
            int n = j >> 3, c16 = j & 7;
            uint32_t off = n * 128 + c16 * 16;
            uint32_t sw  = off ^ ((off >> 3) & 0x70);
            CP_ASYNC16(smem_base + SM_B0 + sw, src0 + (size_t)n * NCOLS + c16 * 8);
        }
        CP_ASYNC_COMMIT();
    }
    float4 regs[8];
    #pragma unroll
    for (int s = 0; s < 8; s++)
        regs[s] = *(const float4*)(ap + (size_t)s * 16 * NCOLS);

    float dacc[8] = {};
    float acc[2][4][4] = {};
    const int swsts = (rbase & 7) << 4;

    for (int i = 0; i < NCHUNK; i++) {
        // prefetch A chunk i+1 into regs
        float4 nregs[8];
        if (i + 1 < NCHUNK) {
            const float* apn = ap + (size_t)(i + 1) * BKC;
            #pragma unroll
            for (int s = 0; s < 8; s++)
                nregs[s] = *(const float4*)(apn + (size_t)s * 16 * NCOLS);
        }
        // prefetch B chunk i+1
        if (i + 1 < NCHUNK) {
            int nb = (i + 1) % 3;
            const __nv_bfloat16* src0 = featT + kbase + (size_t)(i + 1) * BKC;
            #pragma unroll
            for (int s2 = 0; s2 < 2; s2++) {
                int j = tid + 256 * s2;
                int n = j >> 3, c16 = j & 7;
                uint32_t off = n * 128 + c16 * 16;
                uint32_t sw  = off ^ ((off >> 3) & 0x70);
                CP_ASYNC16(smem_base + b_off[nb] + sw, src0 + (size_t)n * NCOLS + c16 * 8);
            }
        }
        CP_ASYNC_COMMIT();

        // convert + STS A chunk i, accumulate exact fp32 degree
        const uint32_t asts = smem_base + a_off[i & 1];
        #pragma unroll
        for (int s = 0; s < 8; s++) {
            float4 v = regs[s];
            dacc[s] += (v.x + v.y) + (v.z + v.w);
            int row = rbase + 16 * s;
            uint32_t off = ((uint32_t)row * 128 + col4 * 8) ^ swsts;
            __nv_bfloat162 p0 = __floats2bfloat162_rn(v.x, v.y);
            __nv_bfloat162 p1 = __floats2bfloat162_rn(v.z, v.w);
            uint32_t u0 = *(uint32_t*)&p0;
            uint32_t u1 = *(uint32_t*)&p1;
            uint64_t pk = (uint64_t)u0 | ((uint64_t)u1 << 32);
            asm volatile("st.shared.b64 [%0], %1;" :: "r"(asts + off), "l"(pk) : "memory");
        }

        CP_ASYNC_WAIT1();       // B chunk i resident
        __syncthreads();        // A STS + B visible to all warps

        // ---- compute chunk i ----
        const uint32_t ab = smem_base + a_off[i & 1];
        const uint32_t bb = smem_base + b_off[i % 3];
        #pragma unroll
        for (int ks = 0; ks < 4; ks++) {
            uint32_t af[2][4], bf[2][4];
            ldsm4(af[0], ab + abaseoff[0] + (((uint32_t)(ks * 32 + akb)) ^ asx[0]));
            ldsm4(af[1], ab + abaseoff[1] + (((uint32_t)(ks * 32 + akb)) ^ asx[1]));
            ldsm4(bf[0], bb + bbaseoff[0] + (((uint32_t)(ks * 32 + bkb)) ^ bsx[0]));
            ldsm4(bf[1], bb + bbaseoff[1] + (((uint32_t)(ks * 32 + bkb)) ^ bsx[1]));
            #pragma unroll
            for (int mf = 0; mf < 2; mf++) {
                mma16816(acc[mf][0], af[mf], &bf[0][0]);
                mma16816(acc[mf][1], af[mf], &bf[0][2]);
                mma16816(acc[mf][2], af[mf], &bf[1][0]);
                mma16816(acc[mf][3], af[mf], &bf[1][2]);
            }
        }
        #pragma unroll
        for (int s = 0; s < 8; s++) regs[s] = nregs[s];
    }

    // ---- epilogue: write C fragments ----
    {
        const int lq = lid >> 2;
        const int lc = (lid & 3) * 2;
        float* po = part + (size_t)kz * NROWS * F;
        #pragma unroll
        for (int mf = 0; mf < 2; mf++) {
            #pragma unroll
            for (int ng = 0; ng < 4; ng++) {
                int r = row0 + wr0 + mf * 16 + lq;
                int c = wc0 + ng * 8 + lc;
                float2 lo = make_float2(acc[mf][ng][0], acc[mf][ng][1]);
                float2 hi = make_float2(acc[mf][ng][2], acc[mf][ng][3]);
                *(float2*)(po + (size_t)r * F + c)       = lo;
                *(float2*)(po + (size_t)(r + 8) * F + c) = hi;
            }
        }
    }
    // ---- degree: reduce across the 16 lanes sharing each row (deterministic) ----
    #pragma unroll
    for (int s = 0; s < 8; s++) {
        #pragma unroll
        for (int m = 8; m >= 1; m >>= 1)
            dacc[s] += __shfl_xor_sync(0xFFFFFFFFu, dacc[s], m);
    }
    if ((lid & 15) == 0) {
        #pragma unroll
        for (int s = 0; s < 8; s++)
            degp[(size_t)kz * NROWS + row0 + rbase + 16 * s] = dacc[s];
    }
}

// ================= Kernel 2: out = [x || (p0+p1)/(deg+1)] @ W^T =================
#define SM2_TOTAL ((128 * 65 + 64 * 128) * 4)

__global__ __launch_bounds__(256, 1)
void sage_proj_kernel(const float* __restrict__ feat,
                      const float* __restrict__ part,
                      const float* __restrict__ degp,
                      const float* __restrict__ W,
                      float* __restrict__ out)
{
    extern __shared__ float sm2[];
    float* Wsm = sm2;                    // [128][65]
    float* dsm = sm2 + 128 * 65;         // [64][128]

    const int tid  = threadIdx.x;
    const int row0 = blockIdx.x * 64;

    for (int idx = tid; idx < OUTF * 128; idx += 256) {
        int o = idx >> 7, k = idx & 127;
        Wsm[k * 65 + o] = W[idx];
    }
    for (int j = tid; j < 64 * 32; j += 256) {
        int r  = j >> 5;
        int c4 = (j & 31) * 4;
        const int gr = row0 + r;
        float4 v;
        if (c4 < 64) {
            v = *(const float4*)(feat + (size_t)gr * F + c4);
        } else {
            int c = c4 - 64;
            float invd = 1.0f / (degp[gr] + degp[NROWS + gr] + 1.0f);
            float4 a = *(const float4*)(part + (size_t)gr * F + c);
            float4 b = *(const float4*)(part + (size_t)NROWS * F + (size_t)gr * F + c);
            v.x = (a.x + b.x) * invd;
            v.y = (a.y + b.y) * invd;
            v.z = (a.z + b.z) * invd;
            v.w = (a.w + b.w) * invd;
        }
        *(float4*)(dsm + r * 128 + c4) = v;
    }
    __syncthreads();

    const int c  = tid & 63;
    const int rg = tid >> 6;
    float acc[16] = {};
    for (int k = 0; k < 128; k += 4) {
        float w0 = Wsm[(k + 0) * 65 + c];
        float w1 = Wsm[(k + 1) * 65 + c];
        float w2 = Wsm[(k + 2) * 65 + c];
        float w3 = Wsm[(k + 3) * 65 + c];
        #pragma unroll
        for (int rr = 0; rr < 16; rr++) {
            float4 d = *(const float4*)(dsm + (rg * 16 + rr) * 128 + k);
            acc[rr] = fmaf(d.x, w0, acc[rr]);
            acc[rr] = fmaf(d.y, w1, acc[rr]);
            acc[rr] = fmaf(d.z, w2, acc[rr]);
            acc[rr] = fmaf(d.w, w3, acc[rr]);
        }
    }
    #pragma unroll
    for (int rr = 0; rr < 16; rr++)
        out[(size_t)(row0 + rg * 16 + rr) * OUTF + c] = acc[rr];
}

// ================= launch =================
extern "C" void kernel_launch(void* const* d_in, const int* in_sizes, int n_in,
                              void* d_out, int out_size)
{
    const float* adj  = (const float*)d_in[0];
    const float* feat = (const float*)d_in[1];
    const float* W    = (const float*)d_in[2];
    float* out = (float*)d_out;

    float* part;  cudaGetSymbolAddress((void**)&part,  g_part);
    float* degp;  cudaGetSymbolAddress((void**)&degp,  g_deg);
    __nv_bfloat16* featT; cudaGetSymbolAddress((void**)&featT, g_featT);

    static bool attr_done = false;
    if (!attr_done) {
        cudaFuncSetAttribute(sage_neigh_mma, cudaFuncAttributeMaxDynamicSharedMemorySize, SM1_TOTAL);
        cudaFuncSetAttribute(sage_proj_kernel, cudaFuncAttributeMaxDynamicSharedMemorySize, SM2_TOTAL);
        attr_done = true;
    }

    sage_featT_kernel<<<NCOLS / 128, 256>>>(feat, featT);
    sage_neigh_mma<<<dim3(NROWS / 128, KSPLIT), 256, SM1_TOTAL>>>(adj, featT, part, degp);
    sage_proj_kernel<<<NROWS / 64, 256, SM2_TOTAL>>>(feat, part, degp, W, out);
}